// round 1
// baseline (speedup 1.0000x reference)
#include <cuda_runtime.h>

// ============================================================================
// Model_49658411876880: conv->argmax grid, threefry categorical sampling,
// ray march, action histogram, softmax.
//
// RNG: reproduces JAX threefry2x32 with jax_threefry_partitionable=True
// (default since JAX 0.4.36):
//   subkey_i   = (y0, y1) of tf2x32((0,42), (0, i))
//   bits[i]    = y0 ^ y1 of tf2x32(key, (0, i))   (32-bit random_bits)
// categorical(key, logits) = argmax(gumbel + logits)
//                          = argmin((-log2 u) * exp(-logits))   [monotone equiv]
// ============================================================================

#define H 128
#define W 128
#define NV 16
#define NA 8
#define NP 64
#define NCALLS (H * W * NP)   // 1,048,576

__device__ __align__(16) unsigned char g_grid[H * W];
__device__ int g_first[NV];
__device__ int g_counts[NA];
__device__ unsigned g_keys[12];          // 6 subkeys, (k0,k1) pairs flat
__device__ float g_wexp[66 * 64];        // exp(-logits), field-major [v][p]
                                          // offsets: obj 0, pos 1024, neg 2048,
                                          //          act 3072, dir 3584, not 4096

__constant__ int c_dr[8] = { 1, 0, -1, 0, 1, -1, 1, -1 };
__constant__ int c_dc[8] = { 0, 1, 0, -1, 1, 1, -1, -1 };

#define TFR(r) { x0 += x1; x1 = __funnelshift_l(x1, x1, (r)); x1 ^= x0; }

__device__ __forceinline__ void tf2x32(unsigned ka, unsigned kb,
                                       unsigned x0, unsigned x1,
                                       unsigned &y0, unsigned &y1) {
    unsigned kc = ka ^ kb ^ 0x1BD11BDAu;
    x0 += ka; x1 += kb;
    TFR(13) TFR(15) TFR(26) TFR(6)
    x0 += kb; x1 += kc + 1u;
    TFR(17) TFR(29) TFR(16) TFR(24)
    x0 += kc; x1 += ka + 2u;
    TFR(13) TFR(15) TFR(26) TFR(6)
    x0 += ka; x1 += kb + 3u;
    TFR(17) TFR(29) TFR(16) TFR(24)
    x0 += kb; x1 += kc + 4u;
    TFR(13) TFR(15) TFR(26) TFR(6)
    x0 += kc; x1 += ka + 5u;
    y0 = x0; y1 = x1;
}

// bits -> uniform [tiny,1) exactly as jax.random.uniform(float32), then the
// argmin key: (-log2 u). (ln2 scale and the gumbel double-log drop out of
// the argmin once logits enter as a precomputed exp(-l) factor.)
__device__ __forceinline__ float gkey(unsigned bits) {
    float f = __uint_as_float((bits >> 9) | 0x3f800000u) - 1.0f;
    f = fmaxf(f, 1.17549435e-38f);
    return -__log2f(f);
}

template <int VF>
__device__ __forceinline__ int sample1(unsigned ka, unsigned kb, unsigned n,
                                       const float* __restrict__ w, int p) {
    unsigned base = n * (unsigned)VF;
    float best = 3.4e38f;
    int bi = 0;
#pragma unroll 2
    for (int v = 0; v < VF; v++) {
        unsigned y0, y1;
        tf2x32(ka, kb, 0u, base + (unsigned)v, y0, y1);
        float a = gkey(y0 ^ y1) * w[(v << 6) + p];
        if (a < best) { best = a; bi = v; }
    }
    return bi;
}

// ---------------------------------------------------------------------------
// Kernel 1: subkeys, exp(-logits) tables, init first/counts
// ---------------------------------------------------------------------------
__global__ void k_setup(const float* __restrict__ w_obj,
                        const float* __restrict__ w_pos,
                        const float* __restrict__ w_neg,
                        const float* __restrict__ w_act,
                        const float* __restrict__ w_dir,
                        const float* __restrict__ w_not) {
    int tid = threadIdx.x;
    int nt = blockDim.x;
    if (tid < 6) {
        unsigned y0, y1;
        tf2x32(0u, 42u, 0u, (unsigned)tid, y0, y1);
        g_keys[2 * tid]     = y0;
        g_keys[2 * tid + 1] = y1;
    }
    if (tid < NV) g_first[tid] = 1 << 30;
    if (tid >= 32 && tid < 32 + NA) g_counts[tid - 32] = 0;

    for (int e = tid; e < 1024; e += nt) { int v = e >> 6, p = e & 63; g_wexp[e]        = expf(-w_obj[p * 16 + v]); }
    for (int e = tid; e < 1024; e += nt) { int v = e >> 6, p = e & 63; g_wexp[1024 + e] = expf(-w_pos[p * 16 + v]); }
    for (int e = tid; e < 1024; e += nt) { int v = e >> 6, p = e & 63; g_wexp[2048 + e] = expf(-w_neg[p * 16 + v]); }
    for (int e = tid; e < 512;  e += nt) { int v = e >> 6, p = e & 63; g_wexp[3072 + e] = expf(-w_act[p * 8 + v]); }
    for (int e = tid; e < 512;  e += nt) { int v = e >> 6, p = e & 63; g_wexp[3584 + e] = expf(-w_dir[p * 8 + v]); }
    for (int e = tid; e < 128;  e += nt) { int v = e >> 6, p = e & 63; g_wexp[4096 + e] = expf(-w_not[p * 2 + v]); }
}

// ---------------------------------------------------------------------------
// Kernel 2: 3x3 SAME conv (cross-correlation) + bias, argmax over 16 channels,
// first (row-major) occurrence per value via atomicMin.
// ---------------------------------------------------------------------------
__global__ void __launch_bounds__(256) k_conv(const float* __restrict__ obs,
                                              const float* __restrict__ cw,
                                              const float* __restrict__ cb) {
    __shared__ float sw[NV * 27];
    __shared__ float sb[NV];
    int tid = threadIdx.x;
    for (int i = tid; i < NV * 27; i += 256) sw[i] = cw[i];
    if (tid < NV) sb[tid] = cb[tid];
    __syncthreads();

    int idx = blockIdx.x * 256 + tid;
    int r = idx >> 7, c = idx & 127;

    float patch[27];
#pragma unroll
    for (int ci = 0; ci < 3; ci++)
#pragma unroll
        for (int kr = 0; kr < 3; kr++)
#pragma unroll
            for (int kc = 0; kc < 3; kc++) {
                int rr = r + kr - 1, cc = c + kc - 1;
                bool ok = ((unsigned)rr < 128u) && ((unsigned)cc < 128u);
                patch[ci * 9 + kr * 3 + kc] = ok ? obs[ci * (H * W) + rr * W + cc] : 0.0f;
            }

    float best = -3.4e38f;
    int bi = 0;
#pragma unroll
    for (int v = 0; v < NV; v++) {
        float acc = sb[v];
#pragma unroll
        for (int j = 0; j < 27; j++) acc += patch[j] * sw[v * 27 + j];
        if (acc > best) { best = acc; bi = v; }  // strict > => first max (jnp.argmax)
    }
    g_grid[idx] = (unsigned char)bi;
    atomicMin(&g_first[bi], idx);
}

// ---------------------------------------------------------------------------
// Kernel 3: main — 6 categorical samples per call, ray march, histogram.
// ---------------------------------------------------------------------------
__global__ void __launch_bounds__(256) k_main() {
    __shared__ __align__(16) unsigned char s_grid[H * W];
    __shared__ float s_wexp[66 * 64];
    __shared__ int s_first[NV];
    __shared__ int s_counts[NA];
    __shared__ unsigned s_keys[12];
    __shared__ int s_dr[8], s_dc[8];

    int tid = threadIdx.x;
    for (int i = tid; i < (H * W) / 16; i += 256)
        ((uint4*)s_grid)[i] = ((const uint4*)g_grid)[i];
    for (int i = tid; i < 66 * 64; i += 256) s_wexp[i] = g_wexp[i];
    if (tid < NV) s_first[tid] = g_first[tid];
    if (tid < 12) s_keys[tid] = g_keys[tid];
    if (tid < NA) { s_counts[tid] = 0; s_dr[tid] = c_dr[tid]; s_dc[tid] = c_dc[tid]; }
    __syncthreads();

    unsigned n = blockIdx.x * 256u + (unsigned)tid;   // call id, grid = exactly NCALLS
    int p = (int)(n & 63u);

    int s_obj = sample1<16>(s_keys[0],  s_keys[1],  n, s_wexp + 0,    p);
    int s_pos = sample1<16>(s_keys[2],  s_keys[3],  n, s_wexp + 1024, p);
    int s_neg = sample1<16>(s_keys[4],  s_keys[5],  n, s_wexp + 2048, p);
    int s_act = sample1<8> (s_keys[6],  s_keys[7],  n, s_wexp + 3072, p);
    int s_dir = sample1<8> (s_keys[8],  s_keys[9],  n, s_wexp + 3584, p);
    int s_not = sample1<2> (s_keys[10], s_keys[11], n, s_wexp + 4096, p);

    int cond = 0;
    int fi = s_first[s_obj];
    if (fi < H * W) {                    // object exists
        int r = fi >> 7, c = fi & 127;
        int dr = s_dr[s_dir], dc = s_dc[s_dir];
#pragma unroll 1
        for (int st = 0; st < 50; st++) {
            r += dr; c += dc;
            if (((unsigned)(r | c)) >= 128u) break;       // out of bounds -> stop, no hit
            int val = s_grid[(r << 7) + c];
            if (val == s_pos) { cond = 1; break; }        // hit_pos checked first
            if (val == s_neg) break;
        }
    }
    cond ^= s_not;                       // is_not flip (s_not in {0,1})

    if (cond) atomicAdd(&s_counts[s_act], 1);
    __syncthreads();
    if (tid < NA) atomicAdd(&g_counts[tid], s_counts[tid]);
}

// ---------------------------------------------------------------------------
// Kernel 4: softmax over 8 action counts
// ---------------------------------------------------------------------------
__global__ void k_final(float* __restrict__ out) {
    if (threadIdx.x == 0) {
        float c[NA], m = -3.4e38f;
#pragma unroll
        for (int i = 0; i < NA; i++) { c[i] = (float)g_counts[i]; m = fmaxf(m, c[i]); }
        float s = 0.0f, e[NA];
#pragma unroll
        for (int i = 0; i < NA; i++) { e[i] = expf(c[i] - m); s += e[i]; }
#pragma unroll
        for (int i = 0; i < NA; i++) out[i] = e[i] / s;
    }
}

// ---------------------------------------------------------------------------
extern "C" void kernel_launch(void* const* d_in, const int* in_sizes, int n_in,
                              void* d_out, int out_size) {
    const float* obs    = (const float*)d_in[0];
    const float* conv_w = (const float*)d_in[1];
    const float* conv_b = (const float*)d_in[2];
    const float* w_obj  = (const float*)d_in[3];
    const float* w_pos  = (const float*)d_in[4];
    const float* w_neg  = (const float*)d_in[5];
    const float* w_act  = (const float*)d_in[6];
    const float* w_dir  = (const float*)d_in[7];
    const float* w_not  = (const float*)d_in[8];

    k_setup<<<1, 256>>>(w_obj, w_pos, w_neg, w_act, w_dir, w_not);
    k_conv<<<(H * W) / 256, 256>>>(obs, conv_w, conv_b);
    k_main<<<NCALLS / 256, 256>>>();
    k_final<<<1, 32>>>((float*)d_out);
}